// round 5
// baseline (speedup 1.0000x reference)
#include <cuda_runtime.h>
#include <cuda_fp16.h>

// Problem constants (fixed by the dataset)
#define NN      50000
#define IN_C    128
#define HID     64
#define HEADS   4
#define OUT_C   16
#define EE      600000
#define ET      650000          // edges + self loops
#define F1      (HEADS*HID)     // 256
#define NEG_SLOPE 0.2f

// ---------------- scratch (static device globals; no allocation) ----------------
__device__ __align__(16) __half g_h1h[NN*F1];   // x @ W1 (fp16 gather table) [N,256]
__device__ __align__(16) float  g_h2[NN*OUT_C]; // layer2 node features       [N,16]
__device__ __align__(16) float  g_asrc1[NN*HEADS];
__device__ __align__(16) float  g_adst1[NN*HEADS];
__device__ float g_asrc2[NN], g_adst2[NN];
// CSR (grouped by dst)
__device__ int g_deg[NN];
__device__ int g_pos[NN];
__device__ int g_off[NN+1];
__device__ int g_srcs[ET];

// ---------------- helpers ----------------
__device__ __forceinline__ float leaky(float v) {
    return fmaxf(v, 0.f) + NEG_SLOPE * fminf(v, 0.f);
}

// ---------------- CSR build ----------------
__global__ void csr_init_kernel() {
    int t = blockIdx.x * blockDim.x + threadIdx.x;
    if (t < NN) g_deg[t] = 1;                     // deg=1 accounts for self loop
}
__global__ void csr_hist_kernel(const int* __restrict__ ei) {
    int eid = blockIdx.x * blockDim.x + threadIdx.x;
    if (eid >= EE) return;
    atomicAdd(&g_deg[ei[EE + eid]], 1);
}
__global__ void csr_scan_kernel() {   // single block, 1024 threads
    __shared__ int sh[1024];
    int t = threadIdx.x;
    const int CH = (NN + 1023) / 1024;
    int base = t * CH;
    int s = 0;
    for (int i = 0; i < CH; i++) { int id = base + i; if (id < NN) s += g_deg[id]; }
    sh[t] = s;
    __syncthreads();
    for (int off = 1; off < 1024; off <<= 1) {
        int v = (t >= off) ? sh[t - off] : 0;
        __syncthreads();
        sh[t] += v;
        __syncthreads();
    }
    int run = sh[t] - s;   // exclusive prefix
    for (int i = 0; i < CH; i++) {
        int id = base + i;
        if (id < NN) { g_off[id] = run; g_pos[id] = run; run += g_deg[id]; }
    }
    if (t == 1023) g_off[NN] = sh[1023];
}
__global__ void csr_scatter_kernel(const int* __restrict__ ei) {
    int eid = blockIdx.x * blockDim.x + threadIdx.x;
    if (eid >= ET) return;
    int s, d;
    if (eid < EE) { s = ei[eid]; d = ei[EE + eid]; }
    else          { s = d = eid - EE; }
    int p = atomicAdd(&g_pos[d], 1);
    g_srcs[p] = s;
}

// ---------------- GEMM1: h1 = x @ W1 (fp16 out) + fused attention logits ----------------
// 128x128 block tile, 8x8 per thread, BK=16, register-staged double buffering
#define BM 128
#define BN 128
#define BK 16
__global__ void __launch_bounds__(256)
gemm1_kernel(const float* __restrict__ x, const float* __restrict__ W,
             const float* __restrict__ att_src, const float* __restrict__ att_dst) {
    __shared__ float xs[2][BK][BM + 4];
    __shared__ float ws[2][BK][BN + 4];
    int tid  = threadIdx.x;
    int row0 = blockIdx.y * BM;
    int col0 = blockIdx.x * BN;
    int ty = tid >> 4, tx = tid & 15;
    float acc[8][8] = {};

    int xr_r0 = (tid >> 2),  xr_c = (tid & 3) * 4;    // x tile: rows xr_r0, xr_r0+64
    int wr_r0 = (tid >> 5),  wr_c = (tid & 31) * 4;   // W tile: rows wr_r0, wr_r0+8

    float4 xr[2], wr[2];
    auto ldg_tiles = [&](int k0) {
        #pragma unroll
        for (int j = 0; j < 2; j++) {
            int gr = row0 + xr_r0 + j * 64;
            xr[j] = (gr < NN) ? *reinterpret_cast<const float4*>(&x[gr * IN_C + k0 + xr_c])
                              : make_float4(0.f, 0.f, 0.f, 0.f);
            wr[j] = *reinterpret_cast<const float4*>(&W[(k0 + wr_r0 + j * 8) * F1 + col0 + wr_c]);
        }
    };
    auto sts_tiles = [&](int b) {
        #pragma unroll
        for (int j = 0; j < 2; j++) {
            int r = xr_r0 + j * 64;
            xs[b][xr_c  ][r] = xr[j].x; xs[b][xr_c+1][r] = xr[j].y;
            xs[b][xr_c+2][r] = xr[j].z; xs[b][xr_c+3][r] = xr[j].w;
            int rw = wr_r0 + j * 8;
            ws[b][rw][wr_c  ] = wr[j].x; ws[b][rw][wr_c+1] = wr[j].y;
            ws[b][rw][wr_c+2] = wr[j].z; ws[b][rw][wr_c+3] = wr[j].w;
        }
    };

    ldg_tiles(0);
    sts_tiles(0);
    __syncthreads();

    const int NK = IN_C / BK;   // 8
    for (int k0 = 0; k0 < NK; k0++) {
        int b = k0 & 1;
        if (k0 + 1 < NK) ldg_tiles((k0 + 1) * BK);
        #pragma unroll
        for (int k = 0; k < BK; k++) {
            float a[8], c[8];
            #pragma unroll
            for (int i = 0; i < 8; i++) a[i] = xs[b][k][ty*8 + i];
            #pragma unroll
            for (int j = 0; j < 8; j++) c[j] = ws[b][k][tx*8 + j];
            #pragma unroll
            for (int i = 0; i < 8; i++)
                #pragma unroll
                for (int j = 0; j < 8; j++)
                    acc[i][j] = fmaf(a[i], c[j], acc[i][j]);
        }
        if (k0 + 1 < NK) sts_tiles(b ^ 1);
        __syncthreads();
    }

    // write h1 as fp16
    #pragma unroll
    for (int i = 0; i < 8; i++) {
        int gr = row0 + ty*8 + i;
        if (gr < NN) {
            __half2 h[4];
            h[0] = __floats2half2_rn(acc[i][0], acc[i][1]);
            h[1] = __floats2half2_rn(acc[i][2], acc[i][3]);
            h[2] = __floats2half2_rn(acc[i][4], acc[i][5]);
            h[3] = __floats2half2_rn(acc[i][6], acc[i][7]);
            *reinterpret_cast<uint4*>(&g_h1h[gr * F1 + col0 + tx*8]) =
                *reinterpret_cast<const uint4*>(h);
        }
    }

    // fused attention-logit epilogue (fp32, from accumulators)
    int head = (col0 >> 6) + (tx >> 3);
    const float4* asp = reinterpret_cast<const float4*>(&att_src[head * HID + (tx & 7) * 8]);
    const float4* adp = reinterpret_cast<const float4*>(&att_dst[head * HID + (tx & 7) * 8]);
    float4 s0 = asp[0], s1 = asp[1];
    float4 d0 = adp[0], d1 = adp[1];
    #pragma unroll
    for (int i = 0; i < 8; i++) {
        float sd = acc[i][0]*s0.x + acc[i][1]*s0.y + acc[i][2]*s0.z + acc[i][3]*s0.w
                 + acc[i][4]*s1.x + acc[i][5]*s1.y + acc[i][6]*s1.z + acc[i][7]*s1.w;
        float dd = acc[i][0]*d0.x + acc[i][1]*d0.y + acc[i][2]*d0.z + acc[i][3]*d0.w
                 + acc[i][4]*d1.x + acc[i][5]*d1.y + acc[i][6]*d1.z + acc[i][7]*d1.w;
        #pragma unroll
        for (int o = 1; o < 8; o <<= 1) {
            sd += __shfl_xor_sync(0xFFFFFFFFu, sd, o);
            dd += __shfl_xor_sync(0xFFFFFFFFu, dd, o);
        }
        int gr = row0 + ty*8 + i;
        if ((tx & 7) == 0 && gr < NN) {
            g_asrc1[gr * HEADS + head] = sd;
            g_adst1[gr * HEADS + head] = dd;
        }
    }
}

// ---------------- fused layer-1 agg + gemm2 + layer-2 logits (one warp per dst node) ----------------
__device__ __forceinline__ void acc_row(float acc[8], float ex, uint4 r) {
    const __half2* p = reinterpret_cast<const __half2*>(&r);
    #pragma unroll
    for (int j = 0; j < 4; j++) {
        float2 f = __half22float2(p[j]);
        acc[2*j]   = fmaf(ex, f.x, acc[2*j]);
        acc[2*j+1] = fmaf(ex, f.y, acc[2*j+1]);
    }
}
__global__ void __launch_bounds__(256)
agg1_fused_kernel(const float* __restrict__ b1, const float* __restrict__ W2,
                  const float* __restrict__ as2v, const float* __restrict__ ad2v) {
    __shared__ float w2s[F1 * 20];      // pad 20 -> float4-aligned, conflict-free rows
    __shared__ float v_s[8][F1];        // per-warp relu'd out1 row
    __shared__ float s_as2[OUT_C], s_ad2[OUT_C];
    int tid = threadIdx.x;
    for (int i = tid; i < F1 * OUT_C; i += 256) {
        int k = i >> 4, j = i & 15;
        w2s[k * 20 + j] = W2[i];
    }
    if (tid < OUT_C) { s_as2[tid] = as2v[tid]; s_ad2[tid] = ad2v[tid]; }
    __syncthreads();

    int wid = tid >> 5, lane = tid & 31;
    int n = blockIdx.x * 8 + wid;
    if (n >= NN) return;                      // no __syncthreads below this point
    int beg = g_off[n], end = g_off[n+1];
    int hh = lane >> 3;                       // lane handles cols [lane*8, lane*8+8)
    float ad_mine = g_adst1[n * HEADS + (lane & 3)];   // head (lane&3), for exp computers

    // softmax-agg (no max pass: logits are small, softmax is shift-invariant)
    float den = 0.f;
    float acc[8] = {};
    int e = beg;
    for (; e + 3 < end; e += 4) {
        int s0 = g_srcs[e], s1 = g_srcs[e+1], s2 = g_srcs[e+2], s3 = g_srcs[e+3];
        uint4 r0 = *reinterpret_cast<const uint4*>(&g_h1h[s0 * F1 + lane * 8]);
        uint4 r1 = *reinterpret_cast<const uint4*>(&g_h1h[s1 * F1 + lane * 8]);
        uint4 r2 = *reinterpret_cast<const uint4*>(&g_h1h[s2 * F1 + lane * 8]);
        uint4 r3 = *reinterpret_cast<const uint4*>(&g_h1h[s3 * F1 + lane * 8]);
        // lanes 0..15 compute exp for (edge lane>>2, head lane&3)
        float exv = 0.f;
        if (lane < 16) {
            int me = lane >> 2;
            int ss = (me == 0) ? s0 : (me == 1) ? s1 : (me == 2) ? s2 : s3;
            exv = __expf(leaky(g_asrc1[ss * HEADS + (lane & 3)] + ad_mine));
        }
        float ex0 = __shfl_sync(0xFFFFFFFFu, exv,      hh);
        float ex1 = __shfl_sync(0xFFFFFFFFu, exv,  4 + hh);
        float ex2 = __shfl_sync(0xFFFFFFFFu, exv,  8 + hh);
        float ex3 = __shfl_sync(0xFFFFFFFFu, exv, 12 + hh);
        den += (ex0 + ex1) + (ex2 + ex3);
        acc_row(acc, ex0, r0);
        acc_row(acc, ex1, r1);
        acc_row(acc, ex2, r2);
        acc_row(acc, ex3, r3);
    }
    for (; e < end; e++) {
        int s = g_srcs[e];
        uint4 r = *reinterpret_cast<const uint4*>(&g_h1h[s * F1 + lane * 8]);
        float exv = 0.f;
        if (lane < 4) exv = __expf(leaky(g_asrc1[s * HEADS + lane] + ad_mine));
        float ex = __shfl_sync(0xFFFFFFFFu, exv, hh);
        den += ex;
        acc_row(acc, ex, r);
    }

    // relu(alpha-weighted sum + b1) -> per-warp smem row
    float inv = 1.f / den;
    float4 b0 = *reinterpret_cast<const float4*>(&b1[lane * 8]);
    float4 b4 = *reinterpret_cast<const float4*>(&b1[lane * 8 + 4]);
    float4* vp = reinterpret_cast<float4*>(&v_s[wid][lane * 8]);
    vp[0] = make_float4(fmaxf(acc[0]*inv + b0.x, 0.f), fmaxf(acc[1]*inv + b0.y, 0.f),
                        fmaxf(acc[2]*inv + b0.z, 0.f), fmaxf(acc[3]*inv + b0.w, 0.f));
    vp[1] = make_float4(fmaxf(acc[4]*inv + b4.x, 0.f), fmaxf(acc[5]*inv + b4.y, 0.f),
                        fmaxf(acc[6]*inv + b4.z, 0.f), fmaxf(acc[7]*inv + b4.w, 0.f));
    __syncwarp();

    // gemm2 stage: h2 = v @ W2 (k = lane + 32*i mapping, conflict-free)
    float p[OUT_C] = {};
    #pragma unroll
    for (int i = 0; i < 8; i++) {
        int k = lane + 32 * i;
        float v = v_s[wid][k];
        const float4* wr = reinterpret_cast<const float4*>(&w2s[k * 20]);
        float4 wa = wr[0], wb = wr[1], wc = wr[2], wd = wr[3];
        p[0]  = fmaf(v, wa.x, p[0]);  p[1]  = fmaf(v, wa.y, p[1]);
        p[2]  = fmaf(v, wa.z, p[2]);  p[3]  = fmaf(v, wa.w, p[3]);
        p[4]  = fmaf(v, wb.x, p[4]);  p[5]  = fmaf(v, wb.y, p[5]);
        p[6]  = fmaf(v, wb.z, p[6]);  p[7]  = fmaf(v, wb.w, p[7]);
        p[8]  = fmaf(v, wc.x, p[8]);  p[9]  = fmaf(v, wc.y, p[9]);
        p[10] = fmaf(v, wc.z, p[10]); p[11] = fmaf(v, wc.w, p[11]);
        p[12] = fmaf(v, wd.x, p[12]); p[13] = fmaf(v, wd.y, p[13]);
        p[14] = fmaf(v, wd.z, p[14]); p[15] = fmaf(v, wd.w, p[15]);
    }
    #pragma unroll
    for (int j = 0; j < OUT_C; j++)
        #pragma unroll
        for (int o = 16; o; o >>= 1)
            p[j] += __shfl_xor_sync(0xFFFFFFFFu, p[j], o);
    if (lane == 0) {
        float s = 0.f, dd = 0.f;
        #pragma unroll
        for (int j = 0; j < OUT_C; j++) {
            g_h2[n * OUT_C + j] = p[j];
            s  = fmaf(p[j], s_as2[j], s);
            dd = fmaf(p[j], s_ad2[j], dd);
        }
        g_asrc2[n] = s; g_adst2[n] = dd;
    }
}

// ---------------- fused layer-2 softmax + aggregation (one warp per dst node) ----------------
__global__ void __launch_bounds__(256)
agg2_kernel(const float* __restrict__ b2, float* __restrict__ out) {
    int gw   = (blockIdx.x * blockDim.x + threadIdx.x) >> 5;
    int lane = threadIdx.x & 31;
    if (gw >= NN) return;
    int n = gw;
    int beg = g_off[n], end = g_off[n+1];
    float ad = g_adst2[n];

    float den = 0.f, acc = 0.f;
    int e = beg;
    for (; e + 3 < end; e += 4) {
        int s0 = g_srcs[e], s1 = g_srcs[e+1], s2 = g_srcs[e+2], s3 = g_srcs[e+3];
        float h0 = 0.f, h1 = 0.f, h2 = 0.f, h3 = 0.f;
        if (lane < OUT_C) {
            h0 = g_h2[s0 * OUT_C + lane]; h1 = g_h2[s1 * OUT_C + lane];
            h2 = g_h2[s2 * OUT_C + lane]; h3 = g_h2[s3 * OUT_C + lane];
        }
        float exv = 0.f;
        if (lane < 4) {
            int ss = (lane == 0) ? s0 : (lane == 1) ? s1 : (lane == 2) ? s2 : s3;
            exv = __expf(leaky(g_asrc2[ss] + ad));
        }
        float ex0 = __shfl_sync(0xFFFFFFFFu, exv, 0);
        float ex1 = __shfl_sync(0xFFFFFFFFu, exv, 1);
        float ex2 = __shfl_sync(0xFFFFFFFFu, exv, 2);
        float ex3 = __shfl_sync(0xFFFFFFFFu, exv, 3);
        den += (ex0 + ex1) + (ex2 + ex3);
        acc = fmaf(ex0, h0, acc); acc = fmaf(ex1, h1, acc);
        acc = fmaf(ex2, h2, acc); acc = fmaf(ex3, h3, acc);
    }
    for (; e < end; e++) {
        int s = g_srcs[e];
        float hv = (lane < OUT_C) ? g_h2[s * OUT_C + lane] : 0.f;
        float exv = 0.f;
        if (lane == 0) exv = __expf(leaky(g_asrc2[s] + ad));
        float ex = __shfl_sync(0xFFFFFFFFu, exv, 0);
        den += ex;
        acc = fmaf(ex, hv, acc);
    }
    if (lane < OUT_C)
        out[n * OUT_C + lane] = acc / den + b2[lane];
}

// ---------------- launch ----------------
extern "C" void kernel_launch(void* const* d_in, const int* in_sizes, int n_in,
                              void* d_out, int out_size) {
    const float* x    = (const float*)d_in[0];
    const int*   ei   = (const int*)  d_in[1];
    const float* W1   = (const float*)d_in[2];
    const float* as1  = (const float*)d_in[3];
    const float* ad1  = (const float*)d_in[4];
    const float* b1   = (const float*)d_in[5];
    const float* W2   = (const float*)d_in[6];
    const float* as2  = (const float*)d_in[7];
    const float* ad2  = (const float*)d_in[8];
    const float* b2   = (const float*)d_in[9];
    float* out = (float*)d_out;

    // CSR build (grouped by dst)
    csr_init_kernel<<<(NN + 255) / 256, 256>>>();
    csr_hist_kernel<<<(EE + 255) / 256, 256>>>(ei);
    csr_scan_kernel<<<1, 1024>>>();
    csr_scatter_kernel<<<(ET + 255) / 256, 256>>>(ei);

    // layer 1 (gemm + logits), then fused agg1 + gemm2 + logits2
    gemm1_kernel<<<dim3(F1 / BN, (NN + BM - 1) / BM), 256>>>(x, W1, as1, ad1);
    agg1_fused_kernel<<<(NN + 7) / 8, 256>>>(b1, W2, as2, ad2);

    // layer 2 aggregation
    agg2_kernel<<<(NN*32 + 255) / 256, 256>>>(b2, out);
}